// round 4
// baseline (speedup 1.0000x reference)
#include <cuda_runtime.h>

#define B_  2
#define DD  64
#define HH  256
#define WW  256
#define HW  (HH*WW)
#define DHW (DD*HW)
#define PD  (DD+2)
#define PH  (HH+2)
#define PW  (WW+2)
#define PHW (PH*PW)      // 66564

// Zero-padded moving channel (channel 0), per batch. 2 * 4.39M * 4B = 35.1 MB.
__device__ float g_xpad[B_ * PD * PHW];

// ---------------------------------------------------------------------------
// Kernel 1: build the padded moving image (x[:, 0] padded by 1 on each side).
// ---------------------------------------------------------------------------
__global__ void __launch_bounds__(256) pad_kernel(const float* __restrict__ x) {
    int i = blockIdx.x * 256 + threadIdx.x;
    const int total = B_ * PD * PHW;
    if (i >= total) return;
    int b = i / (PD * PHW);
    int r = i - b * (PD * PHW);
    int z = r / PHW; r -= z * PHW;
    int y = r / PW;
    int xx = r - y * PW;
    float v = 0.f;
    if ((unsigned)(z - 1) < (unsigned)DD &&
        (unsigned)(y - 1) < (unsigned)HH &&
        (unsigned)(xx - 1) < (unsigned)WW) {
        v = x[(size_t)b * 2 * DHW + (size_t)(z - 1) * HW + (y - 1) * WW + (xx - 1)];
    }
    g_xpad[i] = v;
}

// ---------------------------------------------------------------------------
// Kernel 2: fused offset-conv + trilinear deformable sampling + fixed copy.
// Block = 256 threads = one full x-row (lane = x), 4 consecutive y, fixed
// (b, z). Conv input tile staged in shared memory (coalesced loads), all 54
// taps always accumulated (zero-filled OOB) with FMA in order kz->ky->kx->c
// (c innermost) -- bit-identical to XLA:CPU Eigen CuboidConvolution and to
// the R3 passing kernel. Downstream elementwise math op-for-op faithful.
// ---------------------------------------------------------------------------
#define ROWPITCH 260
#define NROWS    36            // 2 ch * 3 z * 6 y
#define ROWLEN   258

__global__ void __launch_bounds__(256) reg3d_kernel(
    const float* __restrict__ x,
    const float* __restrict__ wp,   // [3, 2, 3, 3, 3]
    const float* __restrict__ bp,   // [3]
    float* __restrict__ out)        // [2, 2, 64, 256, 256]
{
    __shared__ float stile[NROWS * ROWPITCH];   // [c][dz][dy][col], col = gx+1
    __shared__ float swt[162];
    __shared__ float sb[3];

    const int t = threadIdx.x;
    const int blk = blockIdx.x;          // 8192 = 64(yq) * 64(z) * 2(b)
    const int yq = blk & 63;
    const int z  = (blk >> 6) & 63;
    const int b  = blk >> 12;
    const int y0 = yq << 2;

    if (t < 162) swt[t] = wp[t];
    if (t < 3)   sb[t]  = bp[t];

    const float* xb = x + (size_t)b * 2 * DHW;

    // ---- stage conv input tile: 36 rows x 258 cols, zero-filled OOB ----
    for (int e = t; e < NROWS * ROWLEN; e += 256) {
        int row = e / ROWLEN;
        int col = e - row * ROWLEN;
        int c  = row / 18;
        int r2 = row - c * 18;
        int dz = r2 / 6;
        int dy = r2 - dz * 6;
        int gz = z  + dz - 1;
        int gy = y0 + dy - 1;
        int gx = col - 1;
        float v = 0.f;
        if ((unsigned)gz < (unsigned)DD &&
            (unsigned)gy < (unsigned)HH &&
            (unsigned)gx < (unsigned)WW) {
            v = __ldg(xb + (size_t)c * DHW + (size_t)gz * HW + gy * WW + gx);
        }
        stile[row * ROWPITCH + col] = v;
    }
    __syncthreads();

    const int xi = t;   // this thread's x (0..255)

    // ---- conv: 3 output channels x 4 y-positions, FMA kz->ky->kx->c ----
    float a0[4], a1[4], a2[4];
    #pragma unroll
    for (int j = 0; j < 4; j++) { a0[j] = 0.f; a1[j] = 0.f; a2[j] = 0.f; }

    #pragma unroll
    for (int kz = 0; kz < 3; kz++) {
        float vals[2][6][3];
        #pragma unroll
        for (int c = 0; c < 2; c++)
            #pragma unroll
            for (int dy = 0; dy < 6; dy++)
                #pragma unroll
                for (int dx = 0; dx < 3; dx++)
                    vals[c][dy][dx] =
                        stile[((c * 3 + kz) * 6 + dy) * ROWPITCH + xi + dx];

        #pragma unroll
        for (int ky = 0; ky < 3; ky++)
            #pragma unroll
            for (int kx = 0; kx < 3; kx++)
                #pragma unroll
                for (int c = 0; c < 2; c++) {
                    const int wo = c * 27 + kz * 9 + ky * 3 + kx;
                    float w0 = swt[wo];
                    float w1 = swt[54 + wo];
                    float w2 = swt[108 + wo];
                    #pragma unroll
                    for (int j = 0; j < 4; j++) {
                        float v = vals[c][j + ky][kx];
                        a0[j] = __fmaf_rn(v, w0, a0[j]);
                        a1[j] = __fmaf_rn(v, w1, a1[j]);
                        a2[j] = __fmaf_rn(v, w2, a2[j]);
                    }
                }
    }

    // ---- sampling (op-for-op faithful) ----
    const float* xpad = g_xpad + (size_t)b * PD * PHW;
    const size_t rowbase = (size_t)b * 2 * DHW + (size_t)z * HW;

    #pragma unroll
    for (int j = 0; j < 4; j++) {
        int y = y0 + j;
        float oz = __fadd_rn(a0[j], sb[0]);
        float oy = __fadd_rn(a1[j], sb[1]);
        float ox = __fadd_rn(a2[j], sb[2]);

        float qz = fminf(fmaxf(__fadd_rn((float)(z + 1), oz), 0.f), 64.f);
        float qy = fminf(fmaxf(__fadd_rn((float)(y + 1), oy), 0.f), 256.f);
        float qx = fminf(fmaxf(__fadd_rn((float)(xi + 1), ox), 0.f), 256.f);

        float lz = __fadd_rn(qz, -floorf(qz));
        float ly = __fadd_rn(qy, -floorf(qy));
        float lx = __fadd_rn(qx, -floorf(qx));
        float wz0 = __fadd_rn(1.f, -lz);
        float wy0 = __fadd_rn(1.f, -ly);
        float wx0 = __fadd_rn(1.f, -lx);

        float acc = 0.f;
        #pragma unroll
        for (int dz = 0; dz < 2; dz++) {
            float cz = __fadd_rn(qz, (float)dz);
            float wz = dz ? lz : wz0;
            float czp = __fmul_rn(cz, (float)PHW);
            #pragma unroll
            for (int dy = 0; dy < 2; dy++) {
                float cy  = __fadd_rn(qy, (float)dy);
                float wzy = __fmul_rn(wz, dy ? ly : wy0);
                float czyp = __fadd_rn(czp, __fmul_rn(cy, (float)PW));
                #pragma unroll
                for (int dx = 0; dx < 2; dx++) {
                    float cx   = __fadd_rn(qx, (float)dx);
                    float comb = __fadd_rn(czyp, cx);
                    unsigned idx = (unsigned)comb;   // trunc (astype int32)
                    float wv = __fmul_rn(wzy, dx ? lx : wx0);
                    acc = __fadd_rn(acc, __fmul_rn(__ldg(xpad + idx), wv));
                }
            }
        }

        // channel 0: deformed; channel 1: fixed copy
        size_t o0 = rowbase + (size_t)y * WW + xi;
        out[o0] = acc;
        out[o0 + DHW] = __ldg(xb + DHW + (size_t)z * HW + (size_t)y * WW + xi);
    }
}

// ---------------------------------------------------------------------------
extern "C" void kernel_launch(void* const* d_in, const int* in_sizes, int n_in,
                              void* d_out, int out_size) {
    const float* x  = (const float*)d_in[0];
    const float* wp = (const float*)d_in[1];
    const float* bp = (const float*)d_in[2];
    float* out = (float*)d_out;

    const int pad_total = B_ * PD * PHW;
    pad_kernel<<<(pad_total + 255) / 256, 256>>>(x);

    // 2(b) * 64(z) * 64(y-quads) = 8192 blocks, 256 threads = full x row
    reg3d_kernel<<<8192, 256>>>(x, wp, bp, out);
}

// round 5
// speedup vs baseline: 1.6991x; 1.6991x over previous
#include <cuda_runtime.h>

#define B_  2
#define DD  64
#define HH  256
#define WW  256
#define HW  (HH*WW)
#define DHW (DD*HW)
#define PD  (DD+2)
#define PH  (HH+2)
#define PW  (WW+2)
#define PHW (PH*PW)      // 66564

// Zero-padded moving channel (channel 0), per batch. 2 * 4.39M * 4B = 35.1 MB.
__device__ float g_xpad[B_ * PD * PHW];

// ---------------------------------------------------------------------------
// Kernel 1: padded moving image. Grid (PH, PD, B_), 256 threads cover the
// PW=258 columns in 2 strided steps. No divisions, coalesced stores.
// ---------------------------------------------------------------------------
__global__ void __launch_bounds__(256) pad_kernel(const float* __restrict__ x) {
    const int y = blockIdx.x;          // 0..PH-1
    const int z = blockIdx.y;          // 0..PD-1
    const int b = blockIdx.z;          // 0..B_-1
    const bool zyok = ((unsigned)(z - 1) < (unsigned)DD) &&
                      ((unsigned)(y - 1) < (unsigned)HH);
    const float* src = x + (size_t)b * 2 * DHW + (size_t)(z - 1) * HW + (y - 1) * WW;
    float* dst = g_xpad + (size_t)b * PD * PHW + (size_t)z * PHW + y * PW;
    #pragma unroll
    for (int s = 0; s < 2; s++) {
        int col = threadIdx.x + s * 256;
        if (col < PW) {
            float v = 0.f;
            int gx = col - 1;
            if (zyok && (unsigned)gx < (unsigned)WW) v = __ldg(src + gx);
            dst[col] = v;
        }
    }
}

// ---------------------------------------------------------------------------
// Kernel 2: fused offset-conv + trilinear deformable sampling + fixed copy.
// lane = x (coalesced), each thread computes 4 consecutive y at fixed (b,z).
// All conv LDGs are [Rbase + immediate]; FMA order kz->ky->kx->c (c innermost)
// with exact-zero OOB taps -- bit-identical to the R3 passing kernel.
// ---------------------------------------------------------------------------
__global__ void __launch_bounds__(256) reg3d_kernel(
    const float* __restrict__ x,
    const float* __restrict__ wp,   // [3, 2, 3, 3, 3]
    const float* __restrict__ bp,   // [3]
    float* __restrict__ out)        // [2, 2, 64, 256, 256]
{
    __shared__ float swt[162];
    __shared__ float sb[3];

    const int t = threadIdx.x;             // xi = t (0..255)
    const int blk = blockIdx.x;            // 8192 = 64(yq) * 64(z) * 2(b)
    const int yq = blk & 63;
    const int z  = (blk >> 6) & 63;
    const int b  = blk >> 12;
    const int y0 = yq << 2;

    if (t < 162) swt[t] = wp[t];
    if (t < 3)   sb[t]  = bp[t];
    __syncthreads();

    const int xi = t;
    const float* xb = x + (size_t)b * 2 * DHW;

    // predicates for halo bounds
    bool pz[3], py[6], px[3];
    #pragma unroll
    for (int kz = 0; kz < 3; kz++) pz[kz] = (unsigned)(z + kz - 1) < (unsigned)DD;
    #pragma unroll
    for (int dy = 0; dy < 6; dy++) py[dy] = (unsigned)(y0 + dy - 1) < (unsigned)HH;
    px[0] = (xi >= 1); px[1] = true; px[2] = (xi < 255);

    // per-thread base: (z-1, y0-1, xi) -- only dereferenced where predicated
    const float* base = xb + ((size_t)(z - 1)) * HW + (ptrdiff_t)(y0 - 1) * WW + xi;

    // ---- conv: 3 out channels x 4 y, FMA kz->ky->kx->c ----
    float a0[4], a1[4], a2[4];
    #pragma unroll
    for (int j = 0; j < 4; j++) { a0[j] = 0.f; a1[j] = 0.f; a2[j] = 0.f; }

    #pragma unroll
    for (int kz = 0; kz < 3; kz++) {
        float vals[2][6][3];
        #pragma unroll
        for (int c = 0; c < 2; c++)
            #pragma unroll
            for (int dy = 0; dy < 6; dy++) {
                const bool rowok = pz[kz] && py[dy];
                #pragma unroll
                for (int d = 0; d < 3; d++) {
                    const ptrdiff_t off = (ptrdiff_t)c * DHW + (ptrdiff_t)kz * HW
                                        + (ptrdiff_t)dy * WW + (d - 1);
                    vals[c][dy][d] = (rowok && px[d]) ? __ldg(base + off) : 0.f;
                }
            }

        #pragma unroll
        for (int ky = 0; ky < 3; ky++)
            #pragma unroll
            for (int kx = 0; kx < 3; kx++)
                #pragma unroll
                for (int c = 0; c < 2; c++) {
                    const int wo = c * 27 + kz * 9 + ky * 3 + kx;
                    const float w0 = swt[wo];
                    const float w1 = swt[54 + wo];
                    const float w2 = swt[108 + wo];
                    #pragma unroll
                    for (int j = 0; j < 4; j++) {
                        const float v = vals[c][j + ky][kx];
                        a0[j] = __fmaf_rn(v, w0, a0[j]);
                        a1[j] = __fmaf_rn(v, w1, a1[j]);
                        a2[j] = __fmaf_rn(v, w2, a2[j]);
                    }
                }
    }

    // ---- sampling (op-for-op faithful) ----
    const float* xpad = g_xpad + (size_t)b * PD * PHW;
    const size_t rowbase = (size_t)b * 2 * DHW + (size_t)z * HW;

    #pragma unroll
    for (int j = 0; j < 4; j++) {
        const int y = y0 + j;
        float oz = __fadd_rn(a0[j], sb[0]);
        float oy = __fadd_rn(a1[j], sb[1]);
        float ox = __fadd_rn(a2[j], sb[2]);

        float qz = fminf(fmaxf(__fadd_rn((float)(z + 1), oz), 0.f), 64.f);
        float qy = fminf(fmaxf(__fadd_rn((float)(y + 1), oy), 0.f), 256.f);
        float qx = fminf(fmaxf(__fadd_rn((float)(xi + 1), ox), 0.f), 256.f);

        float lz = __fadd_rn(qz, -floorf(qz));
        float ly = __fadd_rn(qy, -floorf(qy));
        float lx = __fadd_rn(qx, -floorf(qx));
        float wz0 = __fadd_rn(1.f, -lz);
        float wy0 = __fadd_rn(1.f, -ly);
        float wx0 = __fadd_rn(1.f, -lx);

        float acc = 0.f;
        #pragma unroll
        for (int dz = 0; dz < 2; dz++) {
            float cz = __fadd_rn(qz, (float)dz);
            float wz = dz ? lz : wz0;
            float czp = __fmul_rn(cz, (float)PHW);
            #pragma unroll
            for (int dy = 0; dy < 2; dy++) {
                float cy  = __fadd_rn(qy, (float)dy);
                float wzy = __fmul_rn(wz, dy ? ly : wy0);
                float czyp = __fadd_rn(czp, __fmul_rn(cy, (float)PW));
                #pragma unroll
                for (int dx = 0; dx < 2; dx++) {
                    float cx   = __fadd_rn(qx, (float)dx);
                    float comb = __fadd_rn(czyp, cx);
                    unsigned idx = (unsigned)comb;   // trunc (astype int32)
                    float wv = __fmul_rn(wzy, dx ? lx : wx0);
                    acc = __fadd_rn(acc, __fmul_rn(__ldg(xpad + idx), wv));
                }
            }
        }

        const size_t o0 = rowbase + (size_t)y * WW + xi;
        out[o0] = acc;                                           // deformed
        out[o0 + DHW] = __ldg(xb + DHW + (size_t)z * HW + (size_t)y * WW + xi); // fixed
    }
}

// ---------------------------------------------------------------------------
extern "C" void kernel_launch(void* const* d_in, const int* in_sizes, int n_in,
                              void* d_out, int out_size) {
    const float* x  = (const float*)d_in[0];
    const float* wp = (const float*)d_in[1];
    const float* bp = (const float*)d_in[2];
    float* out = (float*)d_out;

    dim3 pgrid(PH, PD, B_);
    pad_kernel<<<pgrid, 256>>>(x);

    // 2(b) * 64(z) * 64(y-quads) = 8192 blocks, 256 threads = full x row
    reg3d_kernel<<<8192, 256>>>(x, wp, bp, out);
}